// round 2
// baseline (speedup 1.0000x reference)
#include <cuda_runtime.h>
#include <math.h>

// Problem constants
#define B      128
#define L      196
#define DTOP   64
#define DLOW   128
#define NE     512
#define NBOOK  15
#define EPSF   1e-8f
#define INV512 (1.0f/512.0f)

// Tiling: block = 32 rows x 512 cols; 8 warps; warp = 8 rows x 256 cols
// thread = 8 rows x 8 cols (4 packed f32x2 column-pairs)
#define BM        32
#define KT        16
#define NTHREADS  256
#define ROWBLOCKS 7   // ceil(196/32)

// Output layout (float32, reference return order)
#define QUANT_OFF 0ll
#define QUANT_CNT (4ll*B*L*DLOW)
#define DIFF_OFF  (QUANT_OFF + QUANT_CNT)   // 12,845,056
#define ID_OFF    (DIFF_OFF + 1)
#define ID_CNT    (4ll*B*L)
#define OT_OFF    (ID_OFF + ID_CNT)

// Device scratch
__device__ float g_q4[B*L*DTOP];                    // top-level quantized codes
__device__ float g_e2_top[NBOOK*NE];                // ||e||^2 top books
__device__ float g_e2_lvl[4*NBOOK*NE];              // ||e||^2 level books
__device__ float g_inve0[NBOOK*NE];                 // 1/(||e||+eps) level-0 (OT)
__device__ float g_embT_top[NBOOK*NE*DTOP];         // transposed top books (K,d)
__device__ float g_embT_lvl[4*NBOOK*NE*DLOW];       // transposed level books

// ---------------------------------------------------------------------------
// Codebook column norms (+ zero the diff accumulator in d_out)
// ---------------------------------------------------------------------------
__global__ void norms_kernel(const float* __restrict__ cb_top,
                             const float* __restrict__ cb_lvl,
                             float* __restrict__ out)
{
    int k = threadIdx.x;
    int book = blockIdx.x;
    if (book == 0 && k == 0) out[DIFF_OFF] = 0.0f;
    if (book < NBOOK) {
        const float* e = cb_top + (size_t)book * DTOP * NE;
        float s = 0.f;
        #pragma unroll 8
        for (int i = 0; i < DTOP; ++i) { float v = e[(size_t)i*NE + k]; s += v*v; }
        g_e2_top[book*NE + k] = s;
    } else {
        int bl = book - NBOOK;
        const float* e = cb_lvl + (size_t)bl * DLOW * NE;
        float s = 0.f;
        #pragma unroll 8
        for (int i = 0; i < DLOW; ++i) { float v = e[(size_t)i*NE + k]; s += v*v; }
        g_e2_lvl[bl*NE + k] = s;
        if (bl < NBOOK) g_inve0[bl*NE + k] = 1.0f / (sqrtf(s) + EPSF);
    }
}

// ---------------------------------------------------------------------------
// Codebook transpose: (d, NE) -> (NE, d) for coalesced row gathers
// grid: (NE/32, 4, 75); block (32, 8)
// ---------------------------------------------------------------------------
__global__ void transpose_kernel(const float* __restrict__ cb_top,
                                 const float* __restrict__ cb_lvl)
{
    __shared__ float tile[32][33];
    int book = blockIdx.z;
    int k0 = blockIdx.x * 32, d0 = blockIdx.y * 32;
    const float* src; float* dst; int OD;
    if (book < NBOOK) {
        if (d0 >= DTOP) return;
        src = cb_top + (size_t)book * DTOP * NE;
        dst = g_embT_top + (size_t)book * NE * DTOP;  OD = DTOP;
    } else {
        int bl = book - NBOOK;
        src = cb_lvl + (size_t)bl * DLOW * NE;
        dst = g_embT_lvl + (size_t)bl * NE * DLOW;    OD = DLOW;
    }
    int tx = threadIdx.x, ty = threadIdx.y;
    #pragma unroll
    for (int dy = ty; dy < 32; dy += 8)
        tile[dy][tx] = src[(size_t)(d0 + dy) * NE + k0 + tx];
    __syncthreads();
    #pragma unroll
    for (int dy = ty; dy < 32; dy += 8)
        dst[(size_t)(k0 + dy) * OD + d0 + tx] = tile[tx][dy];
}

// x element helpers
__device__ __forceinline__ float load_x_low(const float* __restrict__ in,
                                            int j, int b, int l, int c)
{
    if (c < DTOP) return in[((((size_t)j*B + b)*L + l)*DTOP) + c];
    return g_q4[(((size_t)b*L + l)*DTOP) + (c - DTOP)];
}
__device__ __forceinline__ float load_x_top(const float* __restrict__ in,
                                            int b, int l, int c)
{
    return in[((((size_t)4*B + b)*L + l)*DTOP) + c];
}

// ---------------------------------------------------------------------------
// Fused VQ GEMM + argmin + gather + diff (+ OT for level 0)
// ---------------------------------------------------------------------------
template<int KDIM, bool IS_TOP>
__launch_bounds__(NTHREADS, 2)
__global__ void vq_gemm(const float* __restrict__ input_list,
                        const float* __restrict__ cb_top,
                        const float* __restrict__ cb_lvl,
                        const int*   __restrict__ label,
                        float*       __restrict__ out)
{
    __shared__ __align__(16) float e_s[KT][NE];   // 32 KB
    __shared__ __align__(8)  float x_s[BM][KT];   // 2 KB
    __shared__ float minv_s[2][BM];
    __shared__ int   mini_s[2][BM];
    __shared__ float s2_s[BM];
    __shared__ float otm_s[2][BM], otz_s[2][BM], ott_s[2][BM];
    __shared__ int   ind_s[BM];
    __shared__ float dist_s[BM];

    const int rb = blockIdx.x;
    const int b  = blockIdx.y;
    const int s  = blockIdx.z;
    const int j  = IS_TOP ? 4 : (3 - s);
    const int t  = label[b];
    const int rowbase = rb * BM;
    const int tid  = threadIdx.x;
    const int lane = tid & 31;
    const int w    = tid >> 5;
    const int wr   = w >> 1;        // row group 0..3 (8 rows each)
    const int half = w & 1;         // column half
    const int r0   = wr * 8;
    const int colbase = half * 256 + lane * 2;

    const float* emb = IS_TOP ? (cb_top + (size_t)t * DTOP * NE)
                              : (cb_lvl + ((size_t)j * NBOOK + t) * DLOW * NE);

    unsigned long long acc[8][4];
    #pragma unroll
    for (int r = 0; r < 8; ++r)
        #pragma unroll
        for (int p = 0; p < 4; ++p) acc[r][p] = 0ull;

    for (int kb = 0; kb < KDIM; kb += KT) {
        { // codebook tile (KT x 512)
            const float4* src = (const float4*)(emb + (size_t)kb * NE);
            float4* dst = (float4*)&e_s[0][0];
            #pragma unroll
            for (int it = tid; it < KT*NE/4; it += NTHREADS) dst[it] = src[it];
        }
        #pragma unroll
        for (int it = tid; it < BM*KT; it += NTHREADS) {
            int r = it / KT, i = it % KT;
            int l = rowbase + r, c = kb + i;
            float v = 0.f;
            if (l < L) v = IS_TOP ? load_x_top(input_list, b, l, c)
                                  : load_x_low(input_list, j, b, l, c);
            x_s[r][i] = v;
        }
        __syncthreads();

        #pragma unroll
        for (int i = 0; i < KT; i += 2) {
            unsigned long long e0[4], e1[4];
            #pragma unroll
            for (int p = 0; p < 4; ++p)
                e0[p] = *(const unsigned long long*)&e_s[i][colbase + p*64];
            #pragma unroll
            for (int p = 0; p < 4; ++p)
                e1[p] = *(const unsigned long long*)&e_s[i+1][colbase + p*64];
            #pragma unroll
            for (int r = 0; r < 8; ++r) {
                float2 xv = *(const float2*)&x_s[r0 + r][i];
                unsigned long long xp0, xp1;
                asm("mov.b64 %0, {%1,%1};" : "=l"(xp0) : "f"(xv.x));
                asm("mov.b64 %0, {%1,%1};" : "=l"(xp1) : "f"(xv.y));
                #pragma unroll
                for (int p = 0; p < 4; ++p)
                    asm("fma.rn.f32x2 %0, %1, %2, %0;"
                        : "+l"(acc[r][p]) : "l"(xp0), "l"(e0[p]));
                #pragma unroll
                for (int p = 0; p < 4; ++p)
                    asm("fma.rn.f32x2 %0, %1, %2, %0;"
                        : "+l"(acc[r][p]) : "l"(xp1), "l"(e1[p]));
            }
        }
        __syncthreads();
    }

    // ---- Epilogue: per-half argmin / OT partials ----
    const float* e2p = IS_TOP ? (g_e2_top + (size_t)t * NE)
                              : (g_e2_lvl + ((size_t)j * NBOOK + t) * NE);
    float e2v[8];
    #pragma unroll
    for (int p = 0; p < 4; ++p) {
        e2v[2*p]   = e2p[colbase + p*64];
        e2v[2*p+1] = e2p[colbase + p*64 + 1];
    }
    const bool do_ot = (!IS_TOP) && (j == 0);
    float invev[8];
    if (do_ot) {
        const float* ip = g_inve0 + (size_t)t * NE;
        #pragma unroll
        for (int p = 0; p < 4; ++p) {
            invev[2*p]   = ip[colbase + p*64];
            invev[2*p+1] = ip[colbase + p*64 + 1];
        }
    }

    #pragma unroll
    for (int r = 0; r < 8; ++r) {
        int row = r0 + r;
        int l = rowbase + row;
        if (l >= L) continue;   // uniform per warp

        float gv[8];
        #pragma unroll
        for (int p = 0; p < 4; ++p)
            asm("mov.b64 {%0,%1}, %2;" : "=f"(gv[2*p]), "=f"(gv[2*p+1])
                                       : "l"(acc[r][p]));
        // argmin over e2 - 2g within this half (first-index on ties)
        float bv = 3.4e38f; int bi = NE;
        #pragma unroll
        for (int c = 0; c < 8; ++c) {
            int k = colbase + (c >> 1)*64 + (c & 1);
            float v = fmaf(-2.f, gv[c], e2v[c]);
            if (v < bv || (v == bv && k < bi)) { bv = v; bi = k; }
        }
        #pragma unroll
        for (int o = 16; o; o >>= 1) {
            float ov = __shfl_xor_sync(0xffffffffu, bv, o);
            int   oi = __shfl_xor_sync(0xffffffffu, bi, o);
            if (ov < bv || (ov == bv && oi < bi)) { bv = ov; bi = oi; }
        }
        if (lane == 0) { minv_s[half][row] = bv; mini_s[half][row] = bi; }

        if (do_ot) {
            float m = -3.4e38f;
            #pragma unroll
            for (int c = 0; c < 8; ++c) m = fmaxf(m, gv[c] * INV512);
            #pragma unroll
            for (int o = 16; o; o >>= 1)
                m = fmaxf(m, __shfl_xor_sync(0xffffffffu, m, o));
            float Z = 0.f, T = 0.f;
            #pragma unroll
            for (int c = 0; c < 8; ++c) {
                float pe = expf(gv[c] * INV512 - m);
                Z += pe;
                T += gv[c] * invev[c] * pe;
            }
            #pragma unroll
            for (int o = 16; o; o >>= 1) {
                Z += __shfl_xor_sync(0xffffffffu, Z, o);
                T += __shfl_xor_sync(0xffffffffu, T, o);
            }
            if (lane == 0) { otm_s[half][row] = m; otz_s[half][row] = Z; ott_s[half][row] = T; }
        }
    }

    // ||x||^2 per row (half-0 warps)
    if (half == 0) {
        #pragma unroll
        for (int r = 0; r < 8; ++r) {
            int row = r0 + r, l = rowbase + row;
            if (l >= L) continue;
            float s2 = 0.f;
            for (int c = lane; c < KDIM; c += 32) {
                float v = IS_TOP ? load_x_top(input_list, b, l, c)
                                 : load_x_low(input_list, j, b, l, c);
                s2 += v * v;
            }
            #pragma unroll
            for (int o = 16; o; o >>= 1) s2 += __shfl_xor_sync(0xffffffffu, s2, o);
            if (lane == 0) s2_s[row] = s2;
        }
    }
    __syncthreads();

    // Combine halves: one thread per row
    if (tid < BM) {
        int row = tid, l = rowbase + row;
        if (l < L) {
            float v0 = minv_s[0][row], v1 = minv_s[1][row];
            int   i0 = mini_s[0][row], i1 = mini_s[1][row];
            int   bi = (v1 < v0) ? i1 : i0;
            float bv = (v1 < v0) ? v1 : v0;
            float s2 = s2_s[row];
            ind_s[row]  = bi;
            dist_s[row] = s2 + bv;
            if (!IS_TOP)
                out[ID_OFF + ((size_t)s*B + b)*L + l] = (float)bi;
            if (do_ot) {
                float m0 = otm_s[0][row], m1 = otm_s[1][row];
                float m = fmaxf(m0, m1);
                float w0 = expf(m0 - m), w1 = expf(m1 - m);
                float Z = otz_s[0][row]*w0 + otz_s[1][row]*w1;
                float T = ott_s[0][row]*w0 + ott_s[1][row]*w1;
                float invx = 1.0f / (sqrtf(s2) + EPSF);
                out[OT_OFF + (size_t)b*L + l] = (Z - invx * T) / Z;
            }
        }
    }
    __syncthreads();

    if (tid == 0) {
        int nval = L - rowbase; if (nval > BM) nval = BM;
        float sum = 0.f;
        for (int r = 0; r < nval; ++r) sum += dist_s[r];
        atomicAdd(&out[DIFF_OFF], sum * (1.0f / (float)(L * KDIM)));
    }

    // Gather quantized codes from transposed book (coalesced rows)
    const int OD = IS_TOP ? DTOP : DLOW;
    const float* embT = IS_TOP ? (g_embT_top + (size_t)t * NE * DTOP)
                               : (g_embT_lvl + ((size_t)j * NBOOK + t) * NE * DLOW);
    for (int it = tid; it < BM*OD; it += NTHREADS) {
        int r = it / OD, c = it % OD;
        int l = rowbase + r;
        if (l >= L) continue;
        float v = embT[(size_t)ind_s[r] * OD + c];
        if (IS_TOP)
            g_q4[((size_t)b*L + l)*DTOP + c] = v;
        else
            out[QUANT_OFF + (((size_t)s*B + b)*L + l)*DLOW + c] = v;
    }
}

extern "C" void kernel_launch(void* const* d_in, const int* in_sizes, int n_in,
                              void* d_out, int out_size)
{
    const float* input_list = nullptr;
    const float* cb_top     = nullptr;
    const float* cb_lvl     = nullptr;
    const int*   label      = nullptr;

    for (int i = 0; i < n_in; ++i) {
        switch (in_sizes[i]) {
            case 8028160: input_list = (const float*)d_in[i]; break;
            case 491520:  cb_top     = (const float*)d_in[i]; break;
            case 3932160: cb_lvl     = (const float*)d_in[i]; break;
            case 128:     label      = (const int*)  d_in[i]; break;
        }
    }
    if (!input_list || !cb_top || !cb_lvl || !label) return;

    float* out = (float*)d_out;

    norms_kernel<<<NBOOK + 4*NBOOK, NE>>>(cb_top, cb_lvl, out);
    transpose_kernel<<<dim3(NE/32, 4, NBOOK + 4*NBOOK), dim3(32, 8)>>>(cb_top, cb_lvl);
    vq_gemm<DTOP, true ><<<dim3(ROWBLOCKS, B, 1), NTHREADS>>>(input_list, cb_top, cb_lvl, label, out);
    vq_gemm<DLOW, false><<<dim3(ROWBLOCKS, B, 4), NTHREADS>>>(input_list, cb_top, cb_lvl, label, out);
}

// round 3
// speedup vs baseline: 1.0328x; 1.0328x over previous
#include <cuda_runtime.h>
#include <math.h>
#include <stdint.h>

// Problem constants
#define B      128
#define L      196
#define DTOP   64
#define DLOW   128
#define NE     512
#define NBOOK  15
#define EPSF   1e-8f
#define INV512 (1.0f/512.0f)

// Tiling: block = 32 rows x 512 cols; 8 warps; warp = 8 rows x 256 cols
// thread = 8 rows x 8 cols. KT=8 k-steps per tile, double-buffered cp.async.
#define BM        32
#define KT        8
#define NTHREADS  256
#define ROWBLOCKS 7   // ceil(196/32)

// Output layout (float32, reference return order)
#define QUANT_OFF 0ll
#define QUANT_CNT (4ll*B*L*DLOW)
#define DIFF_OFF  (QUANT_OFF + QUANT_CNT)
#define ID_OFF    (DIFF_OFF + 1)
#define ID_CNT    (4ll*B*L)
#define OT_OFF    (ID_OFF + ID_CNT)

// Device scratch
__device__ float g_q4[B*L*DTOP];
__device__ float g_e2_top[NBOOK*NE];
__device__ float g_e2_lvl[4*NBOOK*NE];
__device__ float g_inve0[NBOOK*NE];
__device__ float g_embT_top[NBOOK*NE*DTOP];
__device__ float g_embT_lvl[4*NBOOK*NE*DLOW];

__device__ __forceinline__ unsigned smem_u32(const void* p) {
    unsigned r;
    asm("{.reg .u64 t; cvta.to.shared.u64 t, %1; cvt.u32.u64 %0, t;}"
        : "=r"(r) : "l"(p));
    return r;
}
__device__ __forceinline__ void cp16(unsigned dst, const void* src) {
    asm volatile("cp.async.cg.shared.global [%0], [%1], 16;" :: "r"(dst), "l"(src));
}
#define CP_COMMIT() asm volatile("cp.async.commit_group;" ::: "memory")
#define CP_WAIT0()  asm volatile("cp.async.wait_group 0;"  ::: "memory")

// ---------------------------------------------------------------------------
// Codebook column norms (+ zero the diff accumulator)
// ---------------------------------------------------------------------------
__global__ void norms_kernel(const float* __restrict__ cb_top,
                             const float* __restrict__ cb_lvl,
                             float* __restrict__ out)
{
    int k = threadIdx.x;
    int book = blockIdx.x;
    if (book == 0 && k == 0) out[DIFF_OFF] = 0.0f;
    if (book < NBOOK) {
        const float* e = cb_top + (size_t)book * DTOP * NE;
        float s = 0.f;
        #pragma unroll 8
        for (int i = 0; i < DTOP; ++i) { float v = e[(size_t)i*NE + k]; s += v*v; }
        g_e2_top[book*NE + k] = s;
    } else {
        int bl = book - NBOOK;
        const float* e = cb_lvl + (size_t)bl * DLOW * NE;
        float s = 0.f;
        #pragma unroll 8
        for (int i = 0; i < DLOW; ++i) { float v = e[(size_t)i*NE + k]; s += v*v; }
        g_e2_lvl[bl*NE + k] = s;
        if (bl < NBOOK) g_inve0[bl*NE + k] = 1.0f / (sqrtf(s) + EPSF);
    }
}

// ---------------------------------------------------------------------------
// Codebook transpose: (d, NE) -> (NE, d)
// ---------------------------------------------------------------------------
__global__ void transpose_kernel(const float* __restrict__ cb_top,
                                 const float* __restrict__ cb_lvl)
{
    __shared__ float tile[32][33];
    int book = blockIdx.z;
    int k0 = blockIdx.x * 32, d0 = blockIdx.y * 32;
    const float* src; float* dst; int OD;
    if (book < NBOOK) {
        if (d0 >= DTOP) return;
        src = cb_top + (size_t)book * DTOP * NE;
        dst = g_embT_top + (size_t)book * NE * DTOP;  OD = DTOP;
    } else {
        int bl = book - NBOOK;
        src = cb_lvl + (size_t)bl * DLOW * NE;
        dst = g_embT_lvl + (size_t)bl * NE * DLOW;    OD = DLOW;
    }
    int tx = threadIdx.x, ty = threadIdx.y;
    #pragma unroll
    for (int dy = ty; dy < 32; dy += 8)
        tile[dy][tx] = src[(size_t)(d0 + dy) * NE + k0 + tx];
    __syncthreads();
    #pragma unroll
    for (int dy = ty; dy < 32; dy += 8)
        dst[(size_t)(k0 + dy) * OD + d0 + tx] = tile[tx][dy];
}

// x element helpers
__device__ __forceinline__ float load_x_low(const float* __restrict__ in,
                                            int j, int b, int l, int c)
{
    if (c < DTOP) return in[((((size_t)j*B + b)*L + l)*DTOP) + c];
    return g_q4[(((size_t)b*L + l)*DTOP) + (c - DTOP)];
}
__device__ __forceinline__ float load_x_top(const float* __restrict__ in,
                                            int b, int l, int c)
{
    return in[((((size_t)4*B + b)*L + l)*DTOP) + c];
}

// ---------------------------------------------------------------------------
// Fused VQ GEMM + argmin + gather + diff (+ OT for level 0)
// ---------------------------------------------------------------------------
template<int KDIM, bool IS_TOP>
__launch_bounds__(NTHREADS, 2)
__global__ void vq_gemm(const float* __restrict__ input_list,
                        const float* __restrict__ cb_top,
                        const float* __restrict__ cb_lvl,
                        const int*   __restrict__ label,
                        float*       __restrict__ out)
{
    __shared__ __align__(16) float  e_s[2][KT*NE];    // 2 x 16 KB
    __shared__ __align__(16) float2 x_s[2][BM][KT];   // 4 KB (duplicated pairs)
    __shared__ float minv_s[2][BM];
    __shared__ int   mini_s[2][BM];
    __shared__ float s2_s[BM];
    __shared__ float otm_s[2][BM], otz_s[2][BM], ott_s[2][BM];
    __shared__ int   ind_s[BM];
    __shared__ float dist_s[BM];

    const int rb = blockIdx.x;
    const int b  = blockIdx.y;
    const int s  = blockIdx.z;
    const int j  = IS_TOP ? 4 : (3 - s);
    const int t  = label[b];
    const int rowbase = rb * BM;
    const int tid  = threadIdx.x;
    const int lane = tid & 31;
    const int w    = tid >> 5;
    const int wr   = w >> 1;          // row group 0..3 (8 rows each)
    const int half = w & 1;           // column half
    const int r0   = wr * 8;
    const int colbase = half * 256 + lane * 4;

    const float* emb = IS_TOP ? (cb_top + (size_t)t * DTOP * NE)
                              : (cb_lvl + ((size_t)j * NBOOK + t) * DLOW * NE);

    const unsigned e_smem0 = smem_u32(&e_s[0][0]);
    const unsigned e_smem1 = smem_u32(&e_s[1][0]);

    // x-fill indices: one (row, kstep) per thread
    const int xr = tid >> 3;
    const int xi = tid & 7;
    const int xl = rowbase + xr;

    unsigned long long acc[8][4];
    #pragma unroll
    for (int r = 0; r < 8; ++r)
        #pragma unroll
        for (int p = 0; p < 4; ++p) acc[r][p] = 0ull;

    const int T = KDIM / KT;

    // ---- prologue: fill tile 0 ----
    {
        const float4* src = (const float4*)emb;
        #pragma unroll
        for (int k = 0; k < 4; ++k)
            cp16(e_smem0 + (unsigned)(tid + k*256) * 16u, src + tid + k*256);
        CP_COMMIT();
        float v = 0.f;
        if (xl < L) v = IS_TOP ? load_x_top(input_list, b, xl, xi)
                               : load_x_low(input_list, j, b, xl, xi);
        x_s[0][xr][xi] = make_float2(v, v);
    }

    for (int tt = 0; tt < T; ++tt) {
        const int buf = tt & 1;
        CP_WAIT0();
        __syncthreads();   // e & x for tile tt visible; prior compute done

        if (tt + 1 < T) {  // fill next tile into other buffer
            const int kb = (tt + 1) * KT;
            const unsigned edst = buf ? e_smem0 : e_smem1;
            const float4* src = (const float4*)(emb + (size_t)kb * NE);
            #pragma unroll
            for (int k = 0; k < 4; ++k)
                cp16(edst + (unsigned)(tid + k*256) * 16u, src + tid + k*256);
            CP_COMMIT();
            float v = 0.f;
            int c = kb + xi;
            if (xl < L) v = IS_TOP ? load_x_top(input_list, b, xl, c)
                                   : load_x_low(input_list, j, b, xl, c);
            x_s[buf ^ 1][xr][xi] = make_float2(v, v);
        }

        // ---- compute tile ----
        const float* eb = &e_s[buf][0];
        #pragma unroll
        for (int i = 0; i < KT; i += 2) {
            ulonglong2 ea0 = *(const ulonglong2*)&eb[(i  )*NE + colbase];
            ulonglong2 ea1 = *(const ulonglong2*)&eb[(i  )*NE + colbase + 128];
            ulonglong2 eb0 = *(const ulonglong2*)&eb[(i+1)*NE + colbase];
            ulonglong2 eb1 = *(const ulonglong2*)&eb[(i+1)*NE + colbase + 128];
            #pragma unroll
            for (int r = 0; r < 8; ++r) {
                ulonglong2 xv = *(const ulonglong2*)&x_s[buf][r0 + r][i];
                asm("fma.rn.f32x2 %0, %1, %2, %0;" : "+l"(acc[r][0]) : "l"(xv.x), "l"(ea0.x));
                asm("fma.rn.f32x2 %0, %1, %2, %0;" : "+l"(acc[r][1]) : "l"(xv.x), "l"(ea0.y));
                asm("fma.rn.f32x2 %0, %1, %2, %0;" : "+l"(acc[r][2]) : "l"(xv.x), "l"(ea1.x));
                asm("fma.rn.f32x2 %0, %1, %2, %0;" : "+l"(acc[r][3]) : "l"(xv.x), "l"(ea1.y));
                asm("fma.rn.f32x2 %0, %1, %2, %0;" : "+l"(acc[r][0]) : "l"(xv.y), "l"(eb0.x));
                asm("fma.rn.f32x2 %0, %1, %2, %0;" : "+l"(acc[r][1]) : "l"(xv.y), "l"(eb0.y));
                asm("fma.rn.f32x2 %0, %1, %2, %0;" : "+l"(acc[r][2]) : "l"(xv.y), "l"(eb1.x));
                asm("fma.rn.f32x2 %0, %1, %2, %0;" : "+l"(acc[r][3]) : "l"(xv.y), "l"(eb1.y));
            }
        }
        __syncthreads();   // all warps done with buf before it is refilled
    }

    // ---- Epilogue ----
    // acc[r][p] column mapping: c in 0..7 -> k = colbase + ((c>>2)<<7) + (c&3)
    const float* e2p = IS_TOP ? (g_e2_top + (size_t)t * NE)
                              : (g_e2_lvl + ((size_t)j * NBOOK + t) * NE);
    float e2v[8];
    #pragma unroll
    for (int c = 0; c < 8; ++c)
        e2v[c] = e2p[colbase + ((c >> 2) << 7) + (c & 3)];
    const bool do_ot = (!IS_TOP) && (j == 0);
    float invev[8];
    if (do_ot) {
        const float* ip = g_inve0 + (size_t)t * NE;
        #pragma unroll
        for (int c = 0; c < 8; ++c)
            invev[c] = ip[colbase + ((c >> 2) << 7) + (c & 3)];
    }

    #pragma unroll
    for (int r = 0; r < 8; ++r) {
        int row = r0 + r;
        int l = rowbase + row;
        if (l >= L) continue;   // uniform per warp

        float gv[8];
        #pragma unroll
        for (int p = 0; p < 4; ++p)
            asm("mov.b64 {%0,%1}, %2;" : "=f"(gv[2*p]), "=f"(gv[2*p+1])
                                       : "l"(acc[r][p]));
        // argmin over e2 - 2g within this half (first-index on ties)
        float bv = 3.4e38f; int bi = NE;
        #pragma unroll
        for (int c = 0; c < 8; ++c) {
            int k = colbase + ((c >> 2) << 7) + (c & 3);
            float v = fmaf(-2.f, gv[c], e2v[c]);
            if (v < bv || (v == bv && k < bi)) { bv = v; bi = k; }
        }
        #pragma unroll
        for (int o = 16; o; o >>= 1) {
            float ov = __shfl_xor_sync(0xffffffffu, bv, o);
            int   oi = __shfl_xor_sync(0xffffffffu, bi, o);
            if (ov < bv || (ov == bv && oi < bi)) { bv = ov; bi = oi; }
        }
        if (lane == 0) { minv_s[half][row] = bv; mini_s[half][row] = bi; }

        if (do_ot) {
            float m = -3.4e38f;
            #pragma unroll
            for (int c = 0; c < 8; ++c) m = fmaxf(m, gv[c] * INV512);
            #pragma unroll
            for (int o = 16; o; o >>= 1)
                m = fmaxf(m, __shfl_xor_sync(0xffffffffu, m, o));
            float Z = 0.f, Tt = 0.f;
            #pragma unroll
            for (int c = 0; c < 8; ++c) {
                float pe = expf(gv[c] * INV512 - m);
                Z  += pe;
                Tt += gv[c] * invev[c] * pe;
            }
            #pragma unroll
            for (int o = 16; o; o >>= 1) {
                Z  += __shfl_xor_sync(0xffffffffu, Z,  o);
                Tt += __shfl_xor_sync(0xffffffffu, Tt, o);
            }
            if (lane == 0) { otm_s[half][row] = m; otz_s[half][row] = Z; ott_s[half][row] = Tt; }
        }
    }

    // ||x||^2 per row (half-0 warps)
    if (half == 0) {
        #pragma unroll
        for (int r = 0; r < 8; ++r) {
            int row = r0 + r, l = rowbase + row;
            if (l >= L) continue;
            float s2 = 0.f;
            for (int c = lane; c < KDIM; c += 32) {
                float v = IS_TOP ? load_x_top(input_list, b, l, c)
                                 : load_x_low(input_list, j, b, l, c);
                s2 += v * v;
            }
            #pragma unroll
            for (int o = 16; o; o >>= 1) s2 += __shfl_xor_sync(0xffffffffu, s2, o);
            if (lane == 0) s2_s[row] = s2;
        }
    }
    __syncthreads();

    // Combine halves
    if (tid < BM) {
        int row = tid, l = rowbase + row;
        if (l < L) {
            float v0 = minv_s[0][row], v1 = minv_s[1][row];
            int   i0 = mini_s[0][row], i1 = mini_s[1][row];
            int   bi = (v1 < v0) ? i1 : i0;
            float bv = (v1 < v0) ? v1 : v0;
            float s2 = s2_s[row];
            ind_s[row]  = bi;
            dist_s[row] = s2 + bv;
            if (!IS_TOP)
                out[ID_OFF + ((size_t)s*B + b)*L + l] = (float)bi;
            if (do_ot) {
                float m0 = otm_s[0][row], m1 = otm_s[1][row];
                float m = fmaxf(m0, m1);
                float w0 = expf(m0 - m), w1 = expf(m1 - m);
                float Z  = otz_s[0][row]*w0 + otz_s[1][row]*w1;
                float Tt = ott_s[0][row]*w0 + ott_s[1][row]*w1;
                float invx = 1.0f / (sqrtf(s2) + EPSF);
                out[OT_OFF + (size_t)b*L + l] = (Z - invx * Tt) / Z;
            }
        }
    }
    __syncthreads();

    if (tid == 0) {
        int nval = L - rowbase; if (nval > BM) nval = BM;
        float sum = 0.f;
        for (int r = 0; r < nval; ++r) sum += dist_s[r];
        atomicAdd(&out[DIFF_OFF], sum * (1.0f / (float)(L * KDIM)));
    }

    // Gather quantized codes from transposed book (coalesced rows)
    const int OD = IS_TOP ? DTOP : DLOW;
    const float* embT = IS_TOP ? (g_embT_top + (size_t)t * NE * DTOP)
                               : (g_embT_lvl + ((size_t)j * NBOOK + t) * NE * DLOW);
    for (int it = tid; it < BM*OD; it += NTHREADS) {
        int r = it / OD, c = it % OD;
        int l = rowbase + r;
        if (l >= L) continue;
        float v = embT[(size_t)ind_s[r] * OD + c];
        if (IS_TOP)
            g_q4[((size_t)b*L + l)*DTOP + c] = v;
        else
            out[QUANT_OFF + (((size_t)s*B + b)*L + l)*DLOW + c] = v;
    }
}

extern "C" void kernel_launch(void* const* d_in, const int* in_sizes, int n_in,
                              void* d_out, int out_size)
{
    const float* input_list = nullptr;
    const float* cb_top     = nullptr;
    const float* cb_lvl     = nullptr;
    const int*   label      = nullptr;

    for (int i = 0; i < n_in; ++i) {
        switch (in_sizes[i]) {
            case 8028160: input_list = (const float*)d_in[i]; break;
            case 491520:  cb_top     = (const float*)d_in[i]; break;
            case 3932160: cb_lvl     = (const float*)d_in[i]; break;
            case 128:     label      = (const int*)  d_in[i]; break;
        }
    }
    if (!input_list || !cb_top || !cb_lvl || !label) return;

    float* out = (float*)d_out;

    norms_kernel<<<NBOOK + 4*NBOOK, NE>>>(cb_top, cb_lvl, out);
    transpose_kernel<<<dim3(NE/32, 4, NBOOK + 4*NBOOK), dim3(32, 8)>>>(cb_top, cb_lvl);
    vq_gemm<DTOP, true ><<<dim3(ROWBLOCKS, B, 1), NTHREADS>>>(input_list, cb_top, cb_lvl, label, out);
    vq_gemm<DLOW, false><<<dim3(ROWBLOCKS, B, 4), NTHREADS>>>(input_list, cb_top, cb_lvl, label, out);
}

// round 4
// speedup vs baseline: 1.0353x; 1.0024x over previous
#include <cuda_runtime.h>
#include <math.h>
#include <stdint.h>

// Problem constants
#define B      128
#define L      196
#define DTOP   64
#define DLOW   128
#define NE     512
#define NBOOK  15
#define EPSF   1e-8f
#define INV512 (1.0f/512.0f)

// Tiling: block = 32 rows x 512 cols; 8 warps; warp = 8 rows x 256 cols
// thread = 8 rows x 8 cols. KT=8 k-steps per tile, double-buffered cp.async.
#define BM        32
#define KT        8
#define NTHREADS  256
#define ROWBLOCKS 7   // ceil(196/32)

// Output layout (float32, reference return order)
#define QUANT_OFF 0ll
#define QUANT_CNT (4ll*B*L*DLOW)
#define DIFF_OFF  (QUANT_OFF + QUANT_CNT)
#define ID_OFF    (DIFF_OFF + 1)
#define ID_CNT    (4ll*B*L)
#define OT_OFF    (ID_OFF + ID_CNT)

// Device scratch
__device__ float g_q4[B*L*DTOP];
__device__ float g_e2_top[NBOOK*NE];
__device__ float g_e2_lvl[4*NBOOK*NE];
__device__ float g_inve0[NBOOK*NE];
__device__ float g_embT_top[NBOOK*NE*DTOP];
__device__ float g_embT_lvl[4*NBOOK*NE*DLOW];

__device__ __forceinline__ unsigned smem_u32(const void* p) {
    unsigned r;
    asm("{.reg .u64 t; cvta.to.shared.u64 t, %1; cvt.u32.u64 %0, t;}"
        : "=r"(r) : "l"(p));
    return r;
}
__device__ __forceinline__ void cp16(unsigned dst, const void* src) {
    asm volatile("cp.async.cg.shared.global [%0], [%1], 16;" :: "r"(dst), "l"(src));
}
#define CP_COMMIT() asm volatile("cp.async.commit_group;" ::: "memory")
#define CP_WAIT0()  asm volatile("cp.async.wait_group 0;"  ::: "memory")

// ---------------------------------------------------------------------------
// Codebook column norms (+ zero the diff accumulator)
// ---------------------------------------------------------------------------
__global__ void norms_kernel(const float* __restrict__ cb_top,
                             const float* __restrict__ cb_lvl,
                             float* __restrict__ out)
{
    int k = threadIdx.x;
    int book = blockIdx.x;
    if (book == 0 && k == 0) out[DIFF_OFF] = 0.0f;
    if (book < NBOOK) {
        const float* e = cb_top + (size_t)book * DTOP * NE;
        float s = 0.f;
        #pragma unroll 8
        for (int i = 0; i < DTOP; ++i) { float v = e[(size_t)i*NE + k]; s += v*v; }
        g_e2_top[book*NE + k] = s;
    } else {
        int bl = book - NBOOK;
        const float* e = cb_lvl + (size_t)bl * DLOW * NE;
        float s = 0.f;
        #pragma unroll 8
        for (int i = 0; i < DLOW; ++i) { float v = e[(size_t)i*NE + k]; s += v*v; }
        g_e2_lvl[bl*NE + k] = s;
        if (bl < NBOOK) g_inve0[bl*NE + k] = 1.0f / (sqrtf(s) + EPSF);
    }
}

// ---------------------------------------------------------------------------
// Codebook transpose: (d, NE) -> (NE, d)
// ---------------------------------------------------------------------------
__global__ void transpose_kernel(const float* __restrict__ cb_top,
                                 const float* __restrict__ cb_lvl)
{
    __shared__ float tile[32][33];
    int book = blockIdx.z;
    int k0 = blockIdx.x * 32, d0 = blockIdx.y * 32;
    const float* src; float* dst; int OD;
    if (book < NBOOK) {
        if (d0 >= DTOP) return;
        src = cb_top + (size_t)book * DTOP * NE;
        dst = g_embT_top + (size_t)book * NE * DTOP;  OD = DTOP;
    } else {
        int bl = book - NBOOK;
        src = cb_lvl + (size_t)bl * DLOW * NE;
        dst = g_embT_lvl + (size_t)bl * NE * DLOW;    OD = DLOW;
    }
    int tx = threadIdx.x, ty = threadIdx.y;
    #pragma unroll
    for (int dy = ty; dy < 32; dy += 8)
        tile[dy][tx] = src[(size_t)(d0 + dy) * NE + k0 + tx];
    __syncthreads();
    #pragma unroll
    for (int dy = ty; dy < 32; dy += 8)
        dst[(size_t)(k0 + dy) * OD + d0 + tx] = tile[tx][dy];
}

// x element helpers
__device__ __forceinline__ float load_x_low(const float* __restrict__ in,
                                            int j, int b, int l, int c)
{
    if (c < DTOP) return in[((((size_t)j*B + b)*L + l)*DTOP) + c];
    return g_q4[(((size_t)b*L + l)*DTOP) + (c - DTOP)];
}
__device__ __forceinline__ float load_x_top(const float* __restrict__ in,
                                            int b, int l, int c)
{
    return in[((((size_t)4*B + b)*L + l)*DTOP) + c];
}

// ---------------------------------------------------------------------------
// Fused VQ GEMM + argmin + gather + diff (+ OT for level 0)
// ---------------------------------------------------------------------------
template<int KDIM, bool IS_TOP>
__launch_bounds__(NTHREADS, 2)
__global__ void vq_gemm(const float* __restrict__ input_list,
                        const float* __restrict__ cb_top,
                        const float* __restrict__ cb_lvl,
                        const int*   __restrict__ label,
                        float*       __restrict__ out)
{
    __shared__ __align__(16) float  e_s[2][KT*NE];    // 2 x 16 KB
    __shared__ __align__(16) float2 x_s[2][BM][KT];   // 4 KB (duplicated pairs)
    __shared__ float minv_s[2][BM];
    __shared__ int   mini_s[2][BM];
    __shared__ float s2_s[BM];
    __shared__ float otm_s[2][BM], otz_s[2][BM], ott_s[2][BM];
    __shared__ int   ind_s[BM];
    __shared__ float dist_s[BM];

    const int rb = blockIdx.x;
    const int b  = blockIdx.y;
    const int s  = blockIdx.z;
    const int j  = IS_TOP ? 4 : (3 - s);
    const int t  = label[b];
    const int rowbase = rb * BM;
    const int tid  = threadIdx.x;
    const int lane = tid & 31;
    const int w    = tid >> 5;
    const int wr   = w >> 1;          // row group 0..3 (8 rows each)
    const int half = w & 1;           // column half
    const int r0   = wr * 8;
    const int colbase = half * 256 + lane * 4;

    const float* emb = IS_TOP ? (cb_top + (size_t)t * DTOP * NE)
                              : (cb_lvl + ((size_t)j * NBOOK + t) * DLOW * NE);

    const unsigned e_smem0 = smem_u32(&e_s[0][0]);
    const unsigned e_smem1 = smem_u32(&e_s[1][0]);

    // x-fill indices: one (row, kstep) per thread
    const int xr = tid >> 3;
    const int xi = tid & 7;
    const int xl = rowbase + xr;

    unsigned long long acc[8][4];
    #pragma unroll
    for (int r = 0; r < 8; ++r)
        #pragma unroll
        for (int p = 0; p < 4; ++p) acc[r][p] = 0ull;

    const int T = KDIM / KT;

    // ---- prologue: fill tile 0 ----
    {
        const float4* src = (const float4*)emb;
        #pragma unroll
        for (int k = 0; k < 4; ++k)
            cp16(e_smem0 + (unsigned)(tid + k*256) * 16u, src + tid + k*256);
        CP_COMMIT();
        float v = 0.f;
        if (xl < L) v = IS_TOP ? load_x_top(input_list, b, xl, xi)
                               : load_x_low(input_list, j, b, xl, xi);
        x_s[0][xr][xi] = make_float2(v, v);
    }

    for (int tt = 0; tt < T; ++tt) {
        const int buf = tt & 1;
        CP_WAIT0();
        __syncthreads();   // e & x for tile tt visible; prior compute done

        if (tt + 1 < T) {  // fill next tile into other buffer
            const int kb = (tt + 1) * KT;
            const unsigned edst = buf ? e_smem0 : e_smem1;
            const float4* src = (const float4*)(emb + (size_t)kb * NE);
            #pragma unroll
            for (int k = 0; k < 4; ++k)
                cp16(edst + (unsigned)(tid + k*256) * 16u, src + tid + k*256);
            CP_COMMIT();
            float v = 0.f;
            int c = kb + xi;
            if (xl < L) v = IS_TOP ? load_x_top(input_list, b, xl, c)
                                   : load_x_low(input_list, j, b, xl, c);
            x_s[buf ^ 1][xr][xi] = make_float2(v, v);
        }

        // ---- compute tile ----
        const float* eb = &e_s[buf][0];
        #pragma unroll
        for (int i = 0; i < KT; i += 2) {
            ulonglong2 ea0 = *(const ulonglong2*)&eb[(i  )*NE + colbase];
            ulonglong2 ea1 = *(const ulonglong2*)&eb[(i  )*NE + colbase + 128];
            ulonglong2 eb0 = *(const ulonglong2*)&eb[(i+1)*NE + colbase];
            ulonglong2 eb1 = *(const ulonglong2*)&eb[(i+1)*NE + colbase + 128];
            #pragma unroll
            for (int r = 0; r < 8; ++r) {
                ulonglong2 xv = *(const ulonglong2*)&x_s[buf][r0 + r][i];
                asm("fma.rn.f32x2 %0, %1, %2, %0;" : "+l"(acc[r][0]) : "l"(xv.x), "l"(ea0.x));
                asm("fma.rn.f32x2 %0, %1, %2, %0;" : "+l"(acc[r][1]) : "l"(xv.x), "l"(ea0.y));
                asm("fma.rn.f32x2 %0, %1, %2, %0;" : "+l"(acc[r][2]) : "l"(xv.x), "l"(ea1.x));
                asm("fma.rn.f32x2 %0, %1, %2, %0;" : "+l"(acc[r][3]) : "l"(xv.x), "l"(ea1.y));
                asm("fma.rn.f32x2 %0, %1, %2, %0;" : "+l"(acc[r][0]) : "l"(xv.y), "l"(eb0.x));
                asm("fma.rn.f32x2 %0, %1, %2, %0;" : "+l"(acc[r][1]) : "l"(xv.y), "l"(eb0.y));
                asm("fma.rn.f32x2 %0, %1, %2, %0;" : "+l"(acc[r][2]) : "l"(xv.y), "l"(eb1.x));
                asm("fma.rn.f32x2 %0, %1, %2, %0;" : "+l"(acc[r][3]) : "l"(xv.y), "l"(eb1.y));
            }
        }
        __syncthreads();   // all warps done with buf before it is refilled
    }

    // ---- Epilogue ----
    // acc[r][p] column mapping: c in 0..7 -> k = colbase + ((c>>2)<<7) + (c&3)
    const float* e2p = IS_TOP ? (g_e2_top + (size_t)t * NE)
                              : (g_e2_lvl + ((size_t)j * NBOOK + t) * NE);
    float e2v[8];
    #pragma unroll
    for (int c = 0; c < 8; ++c)
        e2v[c] = e2p[colbase + ((c >> 2) << 7) + (c & 3)];
    const bool do_ot = (!IS_TOP) && (j == 0);
    float invev[8];
    if (do_ot) {
        const float* ip = g_inve0 + (size_t)t * NE;
        #pragma unroll
        for (int c = 0; c < 8; ++c)
            invev[c] = ip[colbase + ((c >> 2) << 7) + (c & 3)];
    }

    #pragma unroll
    for (int r = 0; r < 8; ++r) {
        int row = r0 + r;
        int l = rowbase + row;
        if (l >= L) continue;   // uniform per warp

        float gv[8];
        #pragma unroll
        for (int p = 0; p < 4; ++p)
            asm("mov.b64 {%0,%1}, %2;" : "=f"(gv[2*p]), "=f"(gv[2*p+1])
                                       : "l"(acc[r][p]));
        // argmin over e2 - 2g within this half (first-index on ties)
        float bv = 3.4e38f; int bi = NE;
        #pragma unroll
        for (int c = 0; c < 8; ++c) {
            int k = colbase + ((c >> 2) << 7) + (c & 3);
            float v = fmaf(-2.f, gv[c], e2v[c]);
            if (v < bv || (v == bv && k < bi)) { bv = v; bi = k; }
        }
        #pragma unroll
        for (int o = 16; o; o >>= 1) {
            float ov = __shfl_xor_sync(0xffffffffu, bv, o);
            int   oi = __shfl_xor_sync(0xffffffffu, bi, o);
            if (ov < bv || (ov == bv && oi < bi)) { bv = ov; bi = oi; }
        }
        if (lane == 0) { minv_s[half][row] = bv; mini_s[half][row] = bi; }

        if (do_ot) {
            float m = -3.4e38f;
            #pragma unroll
            for (int c = 0; c < 8; ++c) m = fmaxf(m, gv[c] * INV512);
            #pragma unroll
            for (int o = 16; o; o >>= 1)
                m = fmaxf(m, __shfl_xor_sync(0xffffffffu, m, o));
            float Z = 0.f, Tt = 0.f;
            #pragma unroll
            for (int c = 0; c < 8; ++c) {
                float pe = expf(gv[c] * INV512 - m);
                Z  += pe;
                Tt += gv[c] * invev[c] * pe;
            }
            #pragma unroll
            for (int o = 16; o; o >>= 1) {
                Z  += __shfl_xor_sync(0xffffffffu, Z,  o);
                Tt += __shfl_xor_sync(0xffffffffu, Tt, o);
            }
            if (lane == 0) { otm_s[half][row] = m; otz_s[half][row] = Z; ott_s[half][row] = Tt; }
        }
    }

    // ||x||^2 per row (half-0 warps)
    if (half == 0) {
        #pragma unroll
        for (int r = 0; r < 8; ++r) {
            int row = r0 + r, l = rowbase + row;
            if (l >= L) continue;
            float s2 = 0.f;
            for (int c = lane; c < KDIM; c += 32) {
                float v = IS_TOP ? load_x_top(input_list, b, l, c)
                                 : load_x_low(input_list, j, b, l, c);
                s2 += v * v;
            }
            #pragma unroll
            for (int o = 16; o; o >>= 1) s2 += __shfl_xor_sync(0xffffffffu, s2, o);
            if (lane == 0) s2_s[row] = s2;
        }
    }
    __syncthreads();

    // Combine halves
    if (tid < BM) {
        int row = tid, l = rowbase + row;
        if (l < L) {
            float v0 = minv_s[0][row], v1 = minv_s[1][row];
            int   i0 = mini_s[0][row], i1 = mini_s[1][row];
            int   bi = (v1 < v0) ? i1 : i0;
            float bv = (v1 < v0) ? v1 : v0;
            float s2 = s2_s[row];
            ind_s[row]  = bi;
            dist_s[row] = s2 + bv;
            if (!IS_TOP)
                out[ID_OFF + ((size_t)s*B + b)*L + l] = (float)bi;
            if (do_ot) {
                float m0 = otm_s[0][row], m1 = otm_s[1][row];
                float m = fmaxf(m0, m1);
                float w0 = expf(m0 - m), w1 = expf(m1 - m);
                float Z  = otz_s[0][row]*w0 + otz_s[1][row]*w1;
                float Tt = ott_s[0][row]*w0 + ott_s[1][row]*w1;
                float invx = 1.0f / (sqrtf(s2) + EPSF);
                out[OT_OFF + (size_t)b*L + l] = (Z - invx * Tt) / Z;
            }
        }
    }
    __syncthreads();

    if (tid == 0) {
        int nval = L - rowbase; if (nval > BM) nval = BM;
        float sum = 0.f;
        for (int r = 0; r < nval; ++r) sum += dist_s[r];
        atomicAdd(&out[DIFF_OFF], sum * (1.0f / (float)(L * KDIM)));
    }

    // Gather quantized codes from transposed book (coalesced rows)
    const int OD = IS_TOP ? DTOP : DLOW;
    const float* embT = IS_TOP ? (g_embT_top + (size_t)t * NE * DTOP)
                               : (g_embT_lvl + ((size_t)j * NBOOK + t) * NE * DLOW);
    for (int it = tid; it < BM*OD; it += NTHREADS) {
        int r = it / OD, c = it % OD;
        int l = rowbase + r;
        if (l >= L) continue;
        float v = embT[(size_t)ind_s[r] * OD + c];
        if (IS_TOP)
            g_q4[((size_t)b*L + l)*DTOP + c] = v;
        else
            out[QUANT_OFF + (((size_t)s*B + b)*L + l)*DLOW + c] = v;
    }
}

extern "C" void kernel_launch(void* const* d_in, const int* in_sizes, int n_in,
                              void* d_out, int out_size)
{
    const float* input_list = nullptr;
    const float* cb_top     = nullptr;
    const float* cb_lvl     = nullptr;
    const int*   label      = nullptr;

    for (int i = 0; i < n_in; ++i) {
        switch (in_sizes[i]) {
            case 8028160: input_list = (const float*)d_in[i]; break;
            case 491520:  cb_top     = (const float*)d_in[i]; break;
            case 3932160: cb_lvl     = (const float*)d_in[i]; break;
            case 128:     label      = (const int*)  d_in[i]; break;
        }
    }
    if (!input_list || !cb_top || !cb_lvl || !label) return;

    float* out = (float*)d_out;

    norms_kernel<<<NBOOK + 4*NBOOK, NE>>>(cb_top, cb_lvl, out);
    transpose_kernel<<<dim3(NE/32, 4, NBOOK + 4*NBOOK), dim3(32, 8)>>>(cb_top, cb_lvl);
    vq_gemm<DTOP, true ><<<dim3(ROWBLOCKS, B, 1), NTHREADS>>>(input_list, cb_top, cb_lvl, label, out);
    vq_gemm<DLOW, false><<<dim3(ROWBLOCKS, B, 4), NTHREADS>>>(input_list, cb_top, cb_lvl, label, out);
}

// round 5
// speedup vs baseline: 1.2019x; 1.1609x over previous
#include <cuda_runtime.h>
#include <math.h>
#include <stdint.h>

#define B      128
#define L      196
#define DTOP   64
#define DLOW   128
#define NE     512
#define NBOOK  15
#define EPSF   1e-8f
#define INV512 (1.0f/512.0f)

#define BM        32
#define KT        8
#define NTHREADS  256
#define ROWBLOCKS 7

#define QUANT_OFF 0ll
#define QUANT_CNT (4ll*B*L*DLOW)
#define DIFF_OFF  (QUANT_OFF + QUANT_CNT)
#define ID_OFF    (DIFF_OFF + 1)
#define ID_CNT    (4ll*B*L)
#define OT_OFF    (ID_OFF + ID_CNT)

__device__ float g_q4[B*L*DTOP];
__device__ float g_e2_top[NBOOK*NE];
__device__ float g_e2_lvl[4*NBOOK*NE];
__device__ float g_inve0[NBOOK*NE];
__device__ float g_embT_top[NBOOK*NE*DTOP];
__device__ float g_embT_lvl[4*NBOOK*NE*DLOW];

__device__ __forceinline__ unsigned smem_u32(const void* p) {
    unsigned r;
    asm("{.reg .u64 t; cvta.to.shared.u64 t, %1; cvt.u32.u64 %0, t;}" : "=r"(r) : "l"(p));
    return r;
}
__device__ __forceinline__ void cp16(unsigned dst, const void* src) {
    asm volatile("cp.async.cg.shared.global [%0], [%1], 16;" :: "r"(dst), "l"(src));
}
#define CP_COMMIT() asm volatile("cp.async.commit_group;" ::: "memory")
#define CP_WAIT0()  asm volatile("cp.async.wait_group 0;" ::: "memory")
#define CP_WAIT1()  asm volatile("cp.async.wait_group 1;" ::: "memory")
#define FMA2(a,x,e) asm("fma.rn.f32x2 %0, %1, %2, %0;" : "+l"(a) : "l"(x), "l"(e))

__global__ void norms_kernel(const float* __restrict__ cb_top,
                             const float* __restrict__ cb_lvl,
                             float* __restrict__ out)
{
    int k = threadIdx.x, book = blockIdx.x;
    if (book == 0 && k == 0) out[DIFF_OFF] = 0.0f;
    if (book < NBOOK) {
        const float* e = cb_top + (size_t)book * DTOP * NE;
        float s = 0.f;
        #pragma unroll 8
        for (int i = 0; i < DTOP; ++i) { float v = e[(size_t)i*NE + k]; s += v*v; }
        g_e2_top[book*NE + k] = s;
    } else {
        int bl = book - NBOOK;
        const float* e = cb_lvl + (size_t)bl * DLOW * NE;
        float s = 0.f;
        #pragma unroll 8
        for (int i = 0; i < DLOW; ++i) { float v = e[(size_t)i*NE + k]; s += v*v; }
        g_e2_lvl[bl*NE + k] = s;
        if (bl < NBOOK) g_inve0[bl*NE + k] = 1.0f / (sqrtf(s) + EPSF);
    }
}

__global__ void transpose_kernel(const float* __restrict__ cb_top,
                                 const float* __restrict__ cb_lvl)
{
    __shared__ float tile[32][33];
    int book = blockIdx.z;
    int k0 = blockIdx.x * 32, d0 = blockIdx.y * 32;
    const float* src; float* dst; int OD;
    if (book < NBOOK) {
        if (d0 >= DTOP) return;
        src = cb_top + (size_t)book * DTOP * NE;
        dst = g_embT_top + (size_t)book * NE * DTOP;  OD = DTOP;
    } else {
        int bl = book - NBOOK;
        src = cb_lvl + (size_t)bl * DLOW * NE;
        dst = g_embT_lvl + (size_t)bl * NE * DLOW;    OD = DLOW;
    }
    int tx = threadIdx.x, ty = threadIdx.y;
    #pragma unroll
    for (int dy = ty; dy < 32; dy += 8)
        tile[dy][tx] = src[(size_t)(d0 + dy) * NE + k0 + tx];
    __syncthreads();
    #pragma unroll
    for (int dy = ty; dy < 32; dy += 8)
        dst[(size_t)(k0 + dy) * OD + d0 + tx] = tile[tx][dy];
}

__device__ __forceinline__ float load_x_low(const float* __restrict__ in,
                                            int j, int b, int l, int c)
{
    if (c < DTOP) return in[((((size_t)j*B + b)*L + l)*DTOP) + c];
    return g_q4[(((size_t)b*L + l)*DTOP) + (c - DTOP)];
}
__device__ __forceinline__ float load_x_top(const float* __restrict__ in,
                                            int b, int l, int c)
{
    return in[((((size_t)4*B + b)*L + l)*DTOP) + c];
}

struct Epi {
    float minv[8][BM]; int mini[8][BM];
    float otm[8][BM], otz[8][BM], ott[8][BM];
    int ind[BM]; float dist[BM];
};

template<int KDIM, bool IS_TOP>
__launch_bounds__(NTHREADS, 2)
__global__ void vq_gemm(const float* __restrict__ input_list,
                        const float* __restrict__ cb_top,
                        const float* __restrict__ cb_lvl,
                        const int*   __restrict__ label,
                        float*       __restrict__ out)
{
    __shared__ __align__(16) float e_s[2*KT*NE];    // 32 KB, swizzled
    __shared__ __align__(16) float x_s[KDIM*BM];    // 16/8 KB

    const int rb = blockIdx.x;
    const int b  = blockIdx.y;
    const int s  = blockIdx.z;
    const int j  = IS_TOP ? 4 : (3 - s);
    const int t  = label[b];
    const int rowbase = rb * BM;
    const int tid  = threadIdx.x;
    const int lane = tid & 31;
    const int w    = tid >> 5;
    const int rg4  = (lane >> 2) * 4;     // first of lane's 4 rows
    const int cq   = lane & 3;
    const int colb = w * 64 + cq * 16;    // first of lane's 16 cols

    const float* emb = IS_TOP ? (cb_top + (size_t)t * DTOP * NE)
                              : (cb_lvl + ((size_t)j * NBOOK + t) * DLOW * NE);
    const unsigned e_base = smem_u32(e_s);

    // per-lane swizzled e chunk offsets within a 2048B k-row
    const unsigned cb0 = (unsigned)(colb * 4);
    const unsigned sw0 = (cb0     ) ^ (((cb0     ) >> 3) & 0x70u);
    const unsigned sw1 = (cb0 + 16) ^ (((cb0 + 16) >> 3) & 0x70u);
    const unsigned sw2 = (cb0 + 32) ^ (((cb0 + 32) >> 3) & 0x70u);
    const unsigned sw3 = (cb0 + 48) ^ (((cb0 + 48) >> 3) & 0x70u);

    unsigned long long acc[4][8];
    #pragma unroll
    for (int r = 0; r < 4; ++r)
        #pragma unroll
        for (int p = 0; p < 8; ++p) acc[r][p] = 0ull;

    const int T = KDIM / KT;

#define FILL_E(BUF, TILE) do {                                                 \
    const char* esrc = (const char*)(emb + (size_t)(TILE) * KT * NE);          \
    const unsigned eb_ = e_base + (BUF) * (KT*NE*4);                           \
    _Pragma("unroll")                                                          \
    for (int kk = 0; kk < 4; ++kk) {                                           \
        unsigned off = (unsigned)(tid + kk*256) * 16u;                         \
        cp16(eb_ + (off ^ ((off >> 3) & 0x70u)), esrc + off);                  \
    }                                                                          \
    CP_COMMIT();                                                               \
} while (0)

#define COMPUTE(BUF) do {                                                      \
    const char* ep0 = (const char*)e_s + (BUF)*(KT*NE*4);                      \
    _Pragma("unroll")                                                          \
    for (int i = 0; i < KT; ++i) {                                             \
        float4 xv = *(const float4*)(xk + i*BM);                               \
        ulonglong2 ea = *(const ulonglong2*)(ep0 + sw0 + i*2048);              \
        ulonglong2 eb = *(const ulonglong2*)(ep0 + sw1 + i*2048);              \
        ulonglong2 ec = *(const ulonglong2*)(ep0 + sw2 + i*2048);              \
        ulonglong2 ed = *(const ulonglong2*)(ep0 + sw3 + i*2048);              \
        float xr4[4] = {xv.x, xv.y, xv.z, xv.w};                               \
        _Pragma("unroll")                                                      \
        for (int r = 0; r < 4; ++r) {                                          \
            unsigned long long xp;                                             \
            asm("mov.b64 %0, {%1,%1};" : "=l"(xp) : "f"(xr4[r]));              \
            FMA2(acc[r][0], xp, ea.x); FMA2(acc[r][1], xp, ea.y);              \
            FMA2(acc[r][2], xp, eb.x); FMA2(acc[r][3], xp, eb.y);              \
            FMA2(acc[r][4], xp, ec.x); FMA2(acc[r][5], xp, ec.y);              \
            FMA2(acc[r][6], xp, ed.x); FMA2(acc[r][7], xp, ed.y);              \
        }                                                                      \
    }                                                                          \
    xk += KT*BM;                                                               \
} while (0)

    FILL_E(0, 0);
    // stage all of x once (rows zero-padded beyond L)
    for (int it = tid; it < KDIM*BM; it += NTHREADS) {
        int c = it >> 5, row = it & 31;
        int l = rowbase + row;
        float v = 0.f;
        if (l < L) v = IS_TOP ? load_x_top(input_list, b, l, c)
                              : load_x_low(input_list, j, b, l, c);
        x_s[c*BM + row] = v;
    }

    const float* xk = x_s + rg4;
    for (int tt = 0; tt < T; tt += 2) {
        FILL_E(1, tt + 1);
        CP_WAIT1(); __syncthreads();      // tile tt (buf0) ready
        COMPUTE(0);
        __syncthreads();                  // buf0 free
        if (tt + 2 < T) { FILL_E(0, tt + 2); CP_WAIT1(); }
        else            { CP_WAIT0(); }
        __syncthreads();                  // tile tt+1 (buf1) ready
        COMPUTE(1);
        __syncthreads();                  // buf1 free
    }

    // ---- Epilogue (smem aliased over dead e_s) ----
    Epi* ep = (Epi*)e_s;
    const float* e2p = IS_TOP ? (g_e2_top + (size_t)t * NE)
                              : (g_e2_lvl + ((size_t)j * NBOOK + t) * NE);
    float e2v[16];
    #pragma unroll
    for (int c = 0; c < 16; c += 4)
        *(float4*)&e2v[c] = *(const float4*)&e2p[colb + c];
    const bool do_ot = (!IS_TOP) && (j == 0);
    float invev[16];
    if (do_ot) {
        const float* ip = g_inve0 + (size_t)t * NE;
        #pragma unroll
        for (int c = 0; c < 16; c += 4)
            *(float4*)&invev[c] = *(const float4*)&ip[colb + c];
    }

    #pragma unroll
    for (int r = 0; r < 4; ++r) {
        int row = rg4 + r;
        int l = rowbase + row;

        float gv[16];
        #pragma unroll
        for (int p = 0; p < 8; ++p)
            asm("mov.b64 {%0,%1}, %2;" : "=f"(gv[2*p]), "=f"(gv[2*p+1]) : "l"(acc[r][p]));

        float bv = 3.4e38f; int bi = NE;
        #pragma unroll
        for (int c = 0; c < 16; ++c) {
            float v = fmaf(-2.f, gv[c], e2v[c]);
            if (v < bv || (v == bv && colb + c < bi)) { bv = v; bi = colb + c; }
        }
        #pragma unroll
        for (int o = 1; o <= 2; o <<= 1) {
            float ov = __shfl_xor_sync(0xffffffffu, bv, o);
            int   oi = __shfl_xor_sync(0xffffffffu, bi, o);
            if (ov < bv || (ov == bv && oi < bi)) { bv = ov; bi = oi; }
        }
        if (cq == 0 && l < L) { ep->minv[w][row] = bv; ep->mini[w][row] = bi; }

        if (do_ot) {
            float m = -3.4e38f;
            #pragma unroll
            for (int c = 0; c < 16; ++c) m = fmaxf(m, gv[c] * INV512);
            #pragma unroll
            for (int o = 1; o <= 2; o <<= 1)
                m = fmaxf(m, __shfl_xor_sync(0xffffffffu, m, o));
            float Z = 0.f, Tt = 0.f;
            #pragma unroll
            for (int c = 0; c < 16; ++c) {
                float pe = expf(gv[c] * INV512 - m);
                Z += pe;  Tt += gv[c] * invev[c] * pe;
            }
            #pragma unroll
            for (int o = 1; o <= 2; o <<= 1) {
                Z  += __shfl_xor_sync(0xffffffffu, Z,  o);
                Tt += __shfl_xor_sync(0xffffffffu, Tt, o);
            }
            if (cq == 0 && l < L) { ep->otm[w][row] = m; ep->otz[w][row] = Z; ep->ott[w][row] = Tt; }
        }
    }
    __syncthreads();

    // combine per row (thread tid<32); s2 from staged x
    if (tid < BM) {
        int row = tid, l = rowbase + row;
        if (l < L) {
            float s2 = 0.f;
            #pragma unroll 8
            for (int c = 0; c < KDIM; ++c) { float v = x_s[c*BM + row]; s2 += v*v; }
            float bv = ep->minv[0][row]; int bi = ep->mini[0][row];
            #pragma unroll
            for (int ww = 1; ww < 8; ++ww) {
                float v = ep->minv[ww][row];
                if (v < bv) { bv = v; bi = ep->mini[ww][row]; }
            }
            ep->ind[row]  = bi;
            ep->dist[row] = s2 + bv;
            if (!IS_TOP)
                out[ID_OFF + ((size_t)s*B + b)*L + l] = (float)bi;
            if (do_ot) {
                float m = ep->otm[0][row];
                #pragma unroll
                for (int ww = 1; ww < 8; ++ww) m = fmaxf(m, ep->otm[ww][row]);
                float Z = 0.f, Tt = 0.f;
                #pragma unroll
                for (int ww = 0; ww < 8; ++ww) {
                    float sc = expf(ep->otm[ww][row] - m);
                    Z  += ep->otz[ww][row] * sc;
                    Tt += ep->ott[ww][row] * sc;
                }
                float invx = 1.0f / (sqrtf(s2) + EPSF);
                out[OT_OFF + (size_t)b*L + l] = (Z - invx * Tt) / Z;
            }
        }
    }
    __syncthreads();

    if (tid == 0) {
        int nval = L - rowbase; if (nval > BM) nval = BM;
        float sum = 0.f;
        for (int r = 0; r < nval; ++r) sum += ep->dist[r];
        atomicAdd(&out[DIFF_OFF], sum * (1.0f / (float)(L * KDIM)));
    }

    // gather quantized codes from transposed book
    const int OD = IS_TOP ? DTOP : DLOW;
    const float* embT = IS_TOP ? (g_embT_top + (size_t)t * NE * DTOP)
                               : (g_embT_lvl + ((size_t)j * NBOOK + t) * NE * DLOW);
    for (int it = tid; it < BM*OD; it += NTHREADS) {
        int r = it / OD, c = it % OD;
        int l = rowbase + r;
        if (l >= L) continue;
        float v = embT[(size_t)ep->ind[r] * OD + c];
        if (IS_TOP)
            g_q4[((size_t)b*L + l)*DTOP + c] = v;
        else
            out[QUANT_OFF + (((size_t)s*B + b)*L + l)*DLOW + c] = v;
    }
#undef FILL_E
#undef COMPUTE
}

extern "C" void kernel_launch(void* const* d_in, const int* in_sizes, int n_in,
                              void* d_out, int out_size)
{
    const float* input_list = nullptr;
    const float* cb_top     = nullptr;
    const float* cb_lvl     = nullptr;
    const int*   label      = nullptr;

    for (int i = 0; i < n_in; ++i) {
        switch (in_sizes[i]) {
            case 8028160: input_list = (const float*)d_in[i]; break;
            case 491520:  cb_top     = (const float*)d_in[i]; break;
            case 3932160: cb_lvl     = (const float*)d_in[i]; break;
            case 128:     label      = (const int*)  d_in[i]; break;
        }
    }
    if (!input_list || !cb_top || !cb_lvl || !label) return;

    float* out = (float*)d_out;

    norms_kernel<<<NBOOK + 4*NBOOK, NE>>>(cb_top, cb_lvl, out);
    transpose_kernel<<<dim3(NE/32, 4, NBOOK + 4*NBOOK), dim3(32, 8)>>>(cb_top, cb_lvl);
    vq_gemm<DTOP, true ><<<dim3(ROWBLOCKS, B, 1), NTHREADS>>>(input_list, cb_top, cb_lvl, label, out);
    vq_gemm<DLOW, false><<<dim3(ROWBLOCKS, B, 4), NTHREADS>>>(input_list, cb_top, cb_lvl, label, out);
}

// round 6
// speedup vs baseline: 1.2058x; 1.0032x over previous
#include <cuda_runtime.h>
#include <math.h>
#include <stdint.h>

#define B      128
#define L      196
#define DTOP   64
#define DLOW   128
#define NE     512
#define NBOOK  15
#define EPSF   1e-8f
#define INV512 (1.0f/512.0f)

#define BM        32
#define KT        8
#define NTHREADS  128
#define ROWBLOCKS 7

#define QUANT_OFF 0ll
#define QUANT_CNT (4ll*B*L*DLOW)
#define DIFF_OFF  (QUANT_OFF + QUANT_CNT)
#define ID_OFF    (DIFF_OFF + 1)
#define ID_CNT    (4ll*B*L)
#define OT_OFF    (ID_OFF + ID_CNT)

__device__ float g_q4[B*L*DTOP];
__device__ float g_e2_top[NBOOK*NE];
__device__ float g_e2_lvl[4*NBOOK*NE];
__device__ float g_inve0[NBOOK*NE];
__device__ float g_embT_top[NBOOK*NE*DTOP];
__device__ float g_embT_lvl[4*NBOOK*NE*DLOW];

__device__ __forceinline__ unsigned smem_u32(const void* p) {
    unsigned r;
    asm("{.reg .u64 t; cvta.to.shared.u64 t, %1; cvt.u32.u64 %0, t;}" : "=r"(r) : "l"(p));
    return r;
}
__device__ __forceinline__ void cp16(unsigned dst, const void* src) {
    asm volatile("cp.async.cg.shared.global [%0], [%1], 16;" :: "r"(dst), "l"(src));
}
#define CP_COMMIT() asm volatile("cp.async.commit_group;" ::: "memory")
#define CP_WAIT0()  asm volatile("cp.async.wait_group 0;" ::: "memory")
#define CP_WAIT1()  asm volatile("cp.async.wait_group 1;" ::: "memory")
#define FMA2(a,x,e) asm("fma.rn.f32x2 %0, %1, %2, %0;" : "+l"(a) : "l"(x), "l"(e))

__global__ void norms_kernel(const float* __restrict__ cb_top,
                             const float* __restrict__ cb_lvl,
                             float* __restrict__ out)
{
    int k = threadIdx.x, book = blockIdx.x;
    if (book == 0 && k == 0) out[DIFF_OFF] = 0.0f;
    if (book < NBOOK) {
        const float* e = cb_top + (size_t)book * DTOP * NE;
        float s = 0.f;
        #pragma unroll 8
        for (int i = 0; i < DTOP; ++i) { float v = e[(size_t)i*NE + k]; s += v*v; }
        g_e2_top[book*NE + k] = s;
    } else {
        int bl = book - NBOOK;
        const float* e = cb_lvl + (size_t)bl * DLOW * NE;
        float s = 0.f;
        #pragma unroll 8
        for (int i = 0; i < DLOW; ++i) { float v = e[(size_t)i*NE + k]; s += v*v; }
        g_e2_lvl[bl*NE + k] = s;
        if (bl < NBOOK) g_inve0[bl*NE + k] = 1.0f / (sqrtf(s) + EPSF);
    }
}

__global__ void transpose_kernel(const float* __restrict__ cb_top,
                                 const float* __restrict__ cb_lvl)
{
    __shared__ float tile[32][33];
    int book = blockIdx.z;
    int k0 = blockIdx.x * 32, d0 = blockIdx.y * 32;
    const float* src; float* dst; int OD;
    if (book < NBOOK) {
        if (d0 >= DTOP) return;
        src = cb_top + (size_t)book * DTOP * NE;
        dst = g_embT_top + (size_t)book * NE * DTOP;  OD = DTOP;
    } else {
        int bl = book - NBOOK;
        src = cb_lvl + (size_t)bl * DLOW * NE;
        dst = g_embT_lvl + (size_t)bl * NE * DLOW;    OD = DLOW;
    }
    int tx = threadIdx.x, ty = threadIdx.y;
    #pragma unroll
    for (int dy = ty; dy < 32; dy += 8)
        tile[dy][tx] = src[(size_t)(d0 + dy) * NE + k0 + tx];
    __syncthreads();
    #pragma unroll
    for (int dy = ty; dy < 32; dy += 8)
        dst[(size_t)(k0 + dy) * OD + d0 + tx] = tile[tx][dy];
}

__device__ __forceinline__ float load_x_low(const float* __restrict__ in,
                                            int j, int b, int l, int c)
{
    if (c < DTOP) return in[((((size_t)j*B + b)*L + l)*DTOP) + c];
    return g_q4[(((size_t)b*L + l)*DTOP) + (c - DTOP)];
}
__device__ __forceinline__ float load_x_top(const float* __restrict__ in,
                                            int b, int l, int c)
{
    return in[((((size_t)4*B + b)*L + l)*DTOP) + c];
}

struct Epi {
    float minv[4][BM]; int mini[4][BM];
    float otm[4][BM], otz[4][BM], ott[4][BM];
    int ind[BM]; float dist[BM];
};

// Block: 32 rows x 512 cols, 4 warps. Warp w covers cols [w*128, w*128+128).
// Lane: rg = lane>>3 (4 groups x 8 rows), co = lane&7 (8 groups x 16 cols).
template<int KDIM, bool IS_TOP>
__launch_bounds__(NTHREADS, 2)
__global__ void vq_gemm(const float* __restrict__ input_list,
                        const float* __restrict__ cb_top,
                        const float* __restrict__ cb_lvl,
                        const int*   __restrict__ label,
                        float*       __restrict__ out)
{
    __shared__ __align__(16) float e_s[2*KT*NE];    // 32 KB, swizzled
    __shared__ __align__(16) float x_s[KDIM*BM];    // 16/8 KB

    const int rb = blockIdx.x;
    const int b  = blockIdx.y;
    const int s  = blockIdx.z;
    const int j  = IS_TOP ? 4 : (3 - s);
    const int t  = label[b];
    const int rowbase = rb * BM;
    const int tid  = threadIdx.x;
    const int lane = tid & 31;
    const int w    = tid >> 5;         // 0..3 col band
    const int rg   = lane >> 3;        // 0..3, 8 rows each
    const int co   = lane & 7;         // 0..7, 16 cols each
    const int rg8  = rg * 8;
    const int colb = w * 128 + co * 16;

    const float* emb = IS_TOP ? (cb_top + (size_t)t * DTOP * NE)
                              : (cb_lvl + ((size_t)j * NBOOK + t) * DLOW * NE);
    const unsigned e_base = smem_u32(e_s);

    // lane's 4 swizzled 16B e-chunk offsets within a 2048B k-row
    const unsigned cb0 = (unsigned)(colb * 4);
    const unsigned sw0 = (cb0     ) ^ (((cb0     ) >> 3) & 0x70u);
    const unsigned sw1 = (cb0 + 16) ^ (((cb0 + 16) >> 3) & 0x70u);
    const unsigned sw2 = (cb0 + 32) ^ (((cb0 + 32) >> 3) & 0x70u);
    const unsigned sw3 = (cb0 + 48) ^ (((cb0 + 48) >> 3) & 0x70u);

    unsigned long long acc[8][8];   // 8 rows x 8 col-pairs
    #pragma unroll
    for (int r = 0; r < 8; ++r)
        #pragma unroll
        for (int p = 0; p < 8; ++p) acc[r][p] = 0ull;

    const int T = KDIM / KT;

#define FILL_E(BUF, TILE) do {                                                 \
    const char* esrc = (const char*)(emb + (size_t)(TILE) * KT * NE);          \
    const unsigned eb_ = e_base + (BUF) * (KT*NE*4);                           \
    _Pragma("unroll")                                                          \
    for (int kk = 0; kk < 8; ++kk) {                                           \
        unsigned off = (unsigned)(tid + kk*128) * 16u;                         \
        cp16(eb_ + (off ^ ((off >> 3) & 0x70u)), esrc + off);                  \
    }                                                                          \
    CP_COMMIT();                                                               \
} while (0)

#define COMPUTE(BUF) do {                                                      \
    const char* ep0 = (const char*)e_s + (BUF)*(KT*NE*4);                      \
    _Pragma("unroll")                                                          \
    for (int i = 0; i < KT; ++i) {                                             \
        float4 xa = *(const float4*)(xk + i*BM);                               \
        float4 xb = *(const float4*)(xk + i*BM + 4);                           \
        ulonglong2 ea = *(const ulonglong2*)(ep0 + sw0 + i*2048);              \
        ulonglong2 eb = *(const ulonglong2*)(ep0 + sw1 + i*2048);              \
        ulonglong2 ec = *(const ulonglong2*)(ep0 + sw2 + i*2048);              \
        ulonglong2 ed = *(const ulonglong2*)(ep0 + sw3 + i*2048);              \
        float xr8[8] = {xa.x, xa.y, xa.z, xa.w, xb.x, xb.y, xb.z, xb.w};       \
        _Pragma("unroll")                                                      \
        for (int r = 0; r < 8; ++r) {                                          \
            unsigned long long xp;                                             \
            asm("mov.b64 %0, {%1,%1};" : "=l"(xp) : "f"(xr8[r]));              \
            FMA2(acc[r][0], xp, ea.x); FMA2(acc[r][1], xp, ea.y);              \
            FMA2(acc[r][2], xp, eb.x); FMA2(acc[r][3], xp, eb.y);              \
            FMA2(acc[r][4], xp, ec.x); FMA2(acc[r][5], xp, ec.y);              \
            FMA2(acc[r][6], xp, ed.x); FMA2(acc[r][7], xp, ed.y);              \
        }                                                                      \
    }                                                                          \
    xk += KT*BM;                                                               \
} while (0)

    FILL_E(0, 0);
    // stage all of x once (rows beyond L zero-padded)
    for (int it = tid; it < KDIM*BM; it += NTHREADS) {
        int c = it >> 5, row = it & 31;
        int l = rowbase + row;
        float v = 0.f;
        if (l < L) v = IS_TOP ? load_x_top(input_list, b, l, c)
                              : load_x_low(input_list, j, b, l, c);
        x_s[c*BM + row] = v;
    }

    const float* xk = x_s + rg8;
    for (int tt = 0; tt < T; tt += 2) {
        FILL_E(1, tt + 1);
        CP_WAIT1(); __syncthreads();      // buf0 ready
        COMPUTE(0);
        __syncthreads();                  // buf0 free
        if (tt + 2 < T) { FILL_E(0, tt + 2); CP_WAIT1(); }
        else            { CP_WAIT0(); }
        __syncthreads();                  // buf1 ready
        COMPUTE(1);
        __syncthreads();                  // buf1 free
    }

    // ---- Epilogue (aliased over dead e_s) ----
    Epi* ep = (Epi*)e_s;
    const float* e2p = IS_TOP ? (g_e2_top + (size_t)t * NE)
                              : (g_e2_lvl + ((size_t)j * NBOOK + t) * NE);
    float e2v[16];
    #pragma unroll
    for (int c = 0; c < 16; c += 4)
        *(float4*)&e2v[c] = *(const float4*)&e2p[colb + c];
    const bool do_ot = (!IS_TOP) && (j == 0);
    float invev[16];
    if (do_ot) {
        const float* ip = g_inve0 + (size_t)t * NE;
        #pragma unroll
        for (int c = 0; c < 16; c += 4)
            *(float4*)&invev[c] = *(const float4*)&ip[colb + c];
    }

    #pragma unroll
    for (int r = 0; r < 8; ++r) {
        int row = rg8 + r;
        int l = rowbase + row;

        float gv[16];
        #pragma unroll
        for (int p = 0; p < 8; ++p)
            asm("mov.b64 {%0,%1}, %2;" : "=f"(gv[2*p]), "=f"(gv[2*p+1]) : "l"(acc[r][p]));

        float bv = 3.4e38f; int bi = NE;
        #pragma unroll
        for (int c = 0; c < 16; ++c) {
            float v = fmaf(-2.f, gv[c], e2v[c]);
            if (v < bv || (v == bv && colb + c < bi)) { bv = v; bi = colb + c; }
        }
        // reduce across the 8 co lanes (same rg octet)
        #pragma unroll
        for (int o = 1; o <= 4; o <<= 1) {
            float ov = __shfl_xor_sync(0xffffffffu, bv, o);
            int   oi = __shfl_xor_sync(0xffffffffu, bi, o);
            if (ov < bv || (ov == bv && oi < bi)) { bv = ov; bi = oi; }
        }
        if (co == 0 && l < L) { ep->minv[w][row] = bv; ep->mini[w][row] = bi; }

        if (do_ot) {
            float m = -3.4e38f;
            #pragma unroll
            for (int c = 0; c < 16; ++c) m = fmaxf(m, gv[c] * INV512);
            #pragma unroll
            for (int o = 1; o <= 4; o <<= 1)
                m = fmaxf(m, __shfl_xor_sync(0xffffffffu, m, o));
            float Z = 0.f, Tt = 0.f;
            #pragma unroll
            for (int c = 0; c < 16; ++c) {
                float pe = expf(gv[c] * INV512 - m);
                Z += pe;  Tt += gv[c] * invev[c] * pe;
            }
            #pragma unroll
            for (int o = 1; o <= 4; o <<= 1) {
                Z  += __shfl_xor_sync(0xffffffffu, Z,  o);
                Tt += __shfl_xor_sync(0xffffffffu, Tt, o);
            }
            if (co == 0 && l < L) { ep->otm[w][row] = m; ep->otz[w][row] = Z; ep->ott[w][row] = Tt; }
        }
    }
    __syncthreads();

    // combine the 4 warp (col-band) partials per row; s2 from staged x
    if (tid < BM) {
        int row = tid, l = rowbase + row;
        if (l < L) {
            float s2 = 0.f;
            #pragma unroll 8
            for (int c = 0; c < KDIM; ++c) { float v = x_s[c*BM + row]; s2 += v*v; }
            float bv = ep->minv[0][row]; int bi = ep->mini[0][row];
            #pragma unroll
            for (int ww = 1; ww < 4; ++ww) {
                float v = ep->minv[ww][row];
                if (v < bv) { bv = v; bi = ep->mini[ww][row]; }
            }
            ep->ind[row]  = bi;
            ep->dist[row] = s2 + bv;
            if (!IS_TOP)
                out[ID_OFF + ((size_t)s*B + b)*L + l] = (float)bi;
            if (do_ot) {
                float m = ep->otm[0][row];
                #pragma unroll
                for (int ww = 1; ww < 4; ++ww) m = fmaxf(m, ep->otm[ww][row]);
                float Z = 0.f, Tt = 0.f;
                #pragma unroll
                for (int ww = 0; ww < 4; ++ww) {
                    float sc = expf(ep->otm[ww][row] - m);
                    Z  += ep->otz[ww][row] * sc;
                    Tt += ep->ott[ww][row] * sc;
                }
                float invx = 1.0f / (sqrtf(s2) + EPSF);
                out[OT_OFF + (size_t)b*L + l] = (Z - invx * Tt) / Z;
            }
        }
    }
    __syncthreads();

    if (tid == 0) {
        int nval = L - rowbase; if (nval > BM) nval = BM;
        float sum = 0.f;
        for (int r = 0; r < nval; ++r) sum += ep->dist[r];
        atomicAdd(&out[DIFF_OFF], sum * (1.0f / (float)(L * KDIM)));
    }

    // gather quantized codes from transposed book (coalesced rows)
    const int OD = IS_TOP ? DTOP : DLOW;
    const float* embT = IS_TOP ? (g_embT_top + (size_t)t * NE * DTOP)
                               : (g_embT_lvl + ((size_t)j * NBOOK + t) * NE * DLOW);
    for (int it = tid; it < BM*OD; it += NTHREADS) {
        int r = it / OD, c = it % OD;
        int l = rowbase + r;
        if (l >= L) continue;
        float v = embT[(size_t)ep->ind[r] * OD + c];
        if (IS_TOP)
            g_q4[((size_t)b*L + l)*DTOP + c] = v;
        else
            out[QUANT_OFF + (((size_t)s*B + b)*L + l)*DLOW + c] = v;
    }
#undef FILL_E
#undef COMPUTE
}

extern "C" void kernel_launch(void* const* d_in, const int* in_sizes, int n_in,
                              void* d_out, int out_size)
{
    const float* input_list = nullptr;
    const float* cb_top     = nullptr;
    const float* cb_lvl     = nullptr;
    const int*   label      = nullptr;

    for (int i = 0; i < n_in; ++i) {
        switch (in_sizes[i]) {
            case 8028160: input_list = (const float*)d_in[i]; break;
            case 491520:  cb_top     = (const float*)d_in[i]; break;
            case 3932160: cb_lvl     = (const float*)d_in[i]; break;
            case 128:     label      = (const int*)  d_in[i]; break;
        }
    }
    if (!input_list || !cb_top || !cb_lvl || !label) return;

    float* out = (float*)d_out;

    norms_kernel<<<NBOOK + 4*NBOOK, NE>>>(cb_top, cb_lvl, out);
    transpose_kernel<<<dim3(NE/32, 4, NBOOK + 4*NBOOK), dim3(32, 8)>>>(cb_top, cb_lvl);
    vq_gemm<DTOP, true ><<<dim3(ROWBLOCKS, B, 1), NTHREADS>>>(input_list, cb_top, cb_lvl, label, out);
    vq_gemm<DLOW, false><<<dim3(ROWBLOCKS, B, 4), NTHREADS>>>(input_list, cb_top, cb_lvl, label, out);
}